// round 5
// baseline (speedup 1.0000x reference)
#include <cuda_runtime.h>

// Shapes (fixed by the problem):
//   q:           [B=2, C=64, H=192, W=320]            fp32
//   warped_feat: [B=2, C=64, H=192, W=320, D=32]      fp32
//   out (sim):   [B=2, D=32, H=192, W=320]            fp32
#define B_  2
#define C_  64
#define H_  192
#define W_  320
#define D_  32
#define HW_ (H_ * W_)
#define NPIX (B_ * HW_)            // 122880
#define HP_ (H_ + 2)               // padded
#define WP_ (W_ + 2)
#define PPIX (B_ * HP_ * WP_)      // padded pixel count
#define EPS2_ 1e-24f               // eps^2 for rsqrt(max(x, eps^2))

#define NB_R  (HW_ / 32)           // 1920 reduce blocks per batch
#define NRING 1028                 // border ring cells per batch
#define NB_B  ((NRING + 255) / 256)        // 5 border blocks per batch
#define NB_X  ((H_ / 8) * (W_ / 16))       // 480 box blocks per batch (256 thr)

// Scratch (zero-padded 1-pixel border so the 3x3 box needs no bounds checks).
// g_nk[pp][d] = (num, kk) interleaved -> one LDG.64 fetches both.
__device__ float2 g_nk [(size_t)PPIX * D_];    // ~32 MB
__device__ float  g_qqp[PPIX];                 // padded sum_c q^2

// ---------------------------------------------------------------------------
// reduce body: per-pixel reduction over C for one batch. 8 threads/pixel,
// float4 over d; warp covers 4 consecutive w -> fully coalesced LDG.128.
// ---------------------------------------------------------------------------
__device__ __forceinline__
void reduce_body(const float* __restrict__ q, const float* __restrict__ k,
                 int batch, int blk)
{
    const int tid = threadIdx.x;
    const int grp = tid >> 3;          // pixel within block: 0..31
    const int sub = tid & 7;           // d-quad: 0..7
    const int hw  = blk * 32 + grp;
    const int h   = hw / W_;
    const int w   = hw - h * W_;

    const float* __restrict__ qp = q + (size_t)batch * C_ * HW_ + hw;
    const float* __restrict__ kp = k + ((size_t)batch * C_ * HW_ + hw) * D_ + sub * 4;

    float4 num = make_float4(0.f, 0.f, 0.f, 0.f);
    float4 kk  = make_float4(0.f, 0.f, 0.f, 0.f);
    float  qq  = 0.f;

    const size_t kstride = (size_t)HW_ * D_;

    #pragma unroll 8
    for (int c = 0; c < C_; ++c) {
        const float  qv = __ldg(qp + (size_t)c * HW_);
        const float4 kv = *reinterpret_cast<const float4*>(kp + (size_t)c * kstride);
        num.x = fmaf(qv, kv.x, num.x);
        num.y = fmaf(qv, kv.y, num.y);
        num.z = fmaf(qv, kv.z, num.z);
        num.w = fmaf(qv, kv.w, num.w);
        kk.x  = fmaf(kv.x, kv.x, kk.x);
        kk.y  = fmaf(kv.y, kv.y, kk.y);
        kk.z  = fmaf(kv.z, kv.z, kk.z);
        kk.w  = fmaf(kv.w, kv.w, kk.w);
        qq    = fmaf(qv, qv, qq);
    }

    const size_t pp = ((size_t)batch * HP_ + h + 1) * WP_ + (w + 1);
    float4* o = reinterpret_cast<float4*>(g_nk + pp * D_ + sub * 4);
    o[0] = make_float4(num.x, kk.x, num.y, kk.y);
    o[1] = make_float4(num.z, kk.z, num.w, kk.w);
    if (sub == 0) g_qqp[pp] = qq;
}

// ---------------------------------------------------------------------------
// border body: zero one ring cell of the padded scratch for one batch.
// ---------------------------------------------------------------------------
__device__ __forceinline__ void border_body(int batch, int t)
{
    if (t >= NRING) return;
    int hp, wp;
    if (t < WP_)          { hp = 0;       wp = t; }
    else if (t < 2 * WP_) { hp = H_ + 1;  wp = t - WP_; }
    else { const int j = t - 2 * WP_;     // j in [0, 2*H)
           hp = 1 + (j >> 1);  wp = (j & 1) ? (W_ + 1) : 0; }

    const size_t pp = ((size_t)batch * HP_ + hp) * WP_ + wp;
    float4* o = reinterpret_cast<float4*>(g_nk + pp * D_);
    #pragma unroll
    for (int m = 0; m < 16; ++m) o[m] = make_float4(0.f, 0.f, 0.f, 0.f);
    g_qqp[pp] = 0.f;
}

// ---------------------------------------------------------------------------
// box body: 3x3 box + normalize for one batch tile (16w x 8h), 256 threads.
// Phase A: all 18 column sums staged (54 independent LDG.64/warp -> high MLP).
// qq column sums are lane-invariant broadcast loads; nq fused via rsqrt.
// Phase C: shared transpose -> coalesced [b,d,h,w] stores.
// ---------------------------------------------------------------------------
__device__ __forceinline__ void box_body(float* __restrict__ out, int batch, int blk)
{
    __shared__ float s[8][16][33];

    const int lane = threadIdx.x & 31;          // = d
    const int wid  = threadIdx.x >> 5;          // h within tile: 0..7

    const int wt = blk % (W_ / 16);
    const int ht = blk / (W_ / 16);             // 0..H/8-1
    const int hb = ht * 8;
    const int h  = hb + wid;
    const int w0 = wt * 16;

    const int pitch = WP_ * D_;
    const float2* __restrict__ base =
        g_nk + (((size_t)batch * HP_ + h + 1) * WP_ + w0) * D_ + lane;
    const float* __restrict__ qb =
        g_qqp + ((size_t)batch * HP_ + h + 1) * WP_ + w0;

    float2 cs[18];
    float  qs[18];
    #pragma unroll
    for (int j = 0; j < 18; ++j) {
        const int o = j * D_;
        const float2 a = base[o - pitch];
        const float2 c = base[o];
        const float2 e = base[o + pitch];
        cs[j] = make_float2(a.x + c.x + e.x, a.y + c.y + e.y);
        qs[j] = qb[j - WP_] + qb[j] + qb[j + WP_];
    }

    #pragma unroll
    for (int i = 0; i < 16; ++i) {
        const float num = cs[i].x + cs[i + 1].x + cs[i + 2].x;
        const float kk  = cs[i].y + cs[i + 1].y + cs[i + 2].y;
        const float qq  = qs[i]   + qs[i + 1]   + qs[i + 2];
        s[wid][i][lane] = num * rsqrtf(fmaxf(qq, EPS2_))
                              * rsqrtf(fmaxf(kk, EPS2_));
    }
    __syncthreads();

    // 4096 outputs (8h x 16w x 32d), 16 stores/thread; each warp store is
    // 2 runs of 16 consecutive floats (64B).
    const int ow = threadIdx.x & 15;
    const int rr = threadIdx.x >> 4;            // 0..15
    const size_t obase = (size_t)batch * D_ * HW_ + w0 + ow;
    #pragma unroll
    for (int i = 0; i < 16; ++i) {
        const int idx = i * 16 + rr;            // 0..255 -> (d, hl)
        const int d   = idx >> 3;
        const int hl  = idx & 7;
        out[obase + ((size_t)d * H_ + hb + hl) * W_] = s[hl][ow][d];
    }
}

// ---------------------------------------------------------------------------
// K1: reduce(b=0) + border(b=0)
// K2: reduce(b=1) + border(b=1) + box(b=0)   <- box hides under DRAM-bound reduce
// K3: box(b=1)
// ---------------------------------------------------------------------------
__global__ __launch_bounds__(256, 4)
void dav_k1(const float* __restrict__ q, const float* __restrict__ k)
{
    if (blockIdx.x < NB_R)
        reduce_body(q, k, 0, blockIdx.x);
    else
        border_body(0, (blockIdx.x - NB_R) * 256 + threadIdx.x);
}

__global__ __launch_bounds__(256, 4)
void dav_k2(const float* __restrict__ q, const float* __restrict__ k,
            float* __restrict__ out)
{
    if (blockIdx.x < NB_R)
        reduce_body(q, k, 1, blockIdx.x);
    else if (blockIdx.x < NB_R + NB_B)
        border_body(1, (blockIdx.x - NB_R) * 256 + threadIdx.x);
    else
        box_body(out, 0, blockIdx.x - (NB_R + NB_B));
}

__global__ __launch_bounds__(256, 4)
void dav_k3(float* __restrict__ out)
{
    box_body(out, 1, blockIdx.x);
}

// ---------------------------------------------------------------------------
extern "C" void kernel_launch(void* const* d_in, const int* in_sizes, int n_in,
                              void* d_out, int out_size)
{
    const float* q = (const float*)d_in[0];     // [B,C,H,W]
    const float* k = (const float*)d_in[1];     // [B,C,H,W,D]
    float* out     = (float*)d_out;             // [B,D,H,W]

    dav_k1<<<NB_R + NB_B, 256>>>(q, k);
    dav_k2<<<NB_R + NB_B + NB_X, 256>>>(q, k, out);
    dav_k3<<<NB_X, 256>>>(out);
}